// round 1
// baseline (speedup 1.0000x reference)
#include <cuda_runtime.h>

// ---------------------------------------------------------------------------
// GIN model, fully fp32.
//   h = x @ Win + bin
//   3x: agg[dst] = sum relu(h[src]); z0 = (1+eps)*h + agg
//       z = LN(z0 @ W1 + b1); h += relu(z) @ W2 + b2
//   g = segment_sum(h, batch);  out = relu(g@Ow1+Ob1)@Ow2+Ob2
// ---------------------------------------------------------------------------

#define NN 50000
#define NE 800000
#define DD 128
#define D2 256
#define NG 64
#define NO 10
#define NL 3
#define MBLK 64

__device__ __align__(16) float g_h[NN * DD];
__device__ __align__(16) float g_z0[NN * DD];
__device__ __align__(16) float g_pool[NG * DD];
__device__ int g_rowptr[NN + 1];
__device__ int g_deg[NN];
__device__ int g_cur[NN];
__device__ int g_srcs[NE];
__device__ int g_gstart[NG + 1];

// ------------------------------ CSR build ----------------------------------
__global__ void k_zero() {
    int i = blockIdx.x * blockDim.x + threadIdx.x;
    if (i < NN) { g_deg[i] = 0; g_cur[i] = 0; }
}

__global__ void k_hist(const int* __restrict__ ei) {
    int e = blockIdx.x * blockDim.x + threadIdx.x;
    if (e < NE) atomicAdd(&g_deg[ei[NE + e]], 1);
}

__global__ void k_scan() {
    __shared__ int part[1024];
    int tid = threadIdx.x;
    const int CH = (NN + 1023) / 1024;  // 49
    int base = tid * CH;
    int s = 0;
    for (int i = 0; i < CH; i++) { int idx = base + i; if (idx < NN) s += g_deg[idx]; }
    part[tid] = s;
    __syncthreads();
    for (int off = 1; off < 1024; off <<= 1) {
        int v = (tid >= off) ? part[tid - off] : 0;
        __syncthreads();
        part[tid] += v;
        __syncthreads();
    }
    int run = (tid == 0) ? 0 : part[tid - 1];
    for (int i = 0; i < CH; i++) {
        int idx = base + i;
        if (idx < NN) { g_rowptr[idx] = run; run += g_deg[idx]; }
    }
    if (tid == 1023) g_rowptr[NN] = part[1023];
}

__global__ void k_place(const int* __restrict__ ei) {
    int e = blockIdx.x * blockDim.x + threadIdx.x;
    if (e < NE) {
        int s = ei[e], d = ei[NE + e];
        int p = g_rowptr[d] + atomicAdd(&g_cur[d], 1);
        g_srcs[p] = s;
    }
}

__global__ void k_gstart(const int* __restrict__ batch) {
    int i = blockIdx.x * blockDim.x + threadIdx.x;
    if (i >= NN) return;
    int b = batch[i];
    if (i == 0) {
        for (int g = 0; g <= b; g++) g_gstart[g] = 0;
    } else {
        int pb = batch[i - 1];
        for (int g = pb + 1; g <= b; g++) g_gstart[g] = i;
    }
    if (i == NN - 1) {
        for (int g = b + 1; g <= NG; g++) g_gstart[g] = NN;
    }
}

// ------------------------------ Aggregation --------------------------------
// One warp per node: gather relu(h[src]) rows (float4/lane), fuse (1+eps)*h.
__global__ __launch_bounds__(256) void k_agg(const float* __restrict__ eps) {
    int node = blockIdx.x * 8 + (threadIdx.x >> 5);
    int lane = threadIdx.x & 31;
    if (node >= NN) return;
    int s = g_rowptr[node], e = g_rowptr[node + 1];
    float4 acc = make_float4(0.f, 0.f, 0.f, 0.f);
    for (int i = s; i < e; i++) {
        int src = g_srcs[i];
        float4 v = *(const float4*)(g_h + src * DD + lane * 4);
        acc.x += fmaxf(v.x, 0.f);
        acc.y += fmaxf(v.y, 0.f);
        acc.z += fmaxf(v.z, 0.f);
        acc.w += fmaxf(v.w, 0.f);
    }
    float k1 = 1.0f + eps[0];
    float4 hv = *(const float4*)(g_h + node * DD + lane * 4);
    float4 o;
    o.x = fmaf(k1, hv.x, acc.x);
    o.y = fmaf(k1, hv.y, acc.y);
    o.z = fmaf(k1, hv.z, acc.z);
    o.w = fmaf(k1, hv.w, acc.w);
    *(float4*)(g_z0 + node * DD + lane * 4) = o;
}

// ------------------------------ Input GEMM ---------------------------------
// h = x @ Win + bin.  64-row tile, W fully in smem, 8x4 register tile.
__global__ __launch_bounds__(256) void k_lin(const float* __restrict__ X,
                                             const float* __restrict__ W,
                                             const float* __restrict__ bias) {
    extern __shared__ float sm[];
    float* Ws = sm;             // 128*128
    float* As = sm + DD * DD;   // 128*64, transposed [k][r]
    int tid = threadIdx.x;
    int tx = tid & 31, ty = tid >> 5;
    int rowBase = blockIdx.x * MBLK;

    {
        const float4* Wv = (const float4*)W;
        float4* Sv = (float4*)Ws;
#pragma unroll
        for (int i = 0; i < 16; i++) Sv[tid + i * 256] = Wv[tid + i * 256];
    }
    {
        int r = tid & 63, kq = tid >> 6;
        int grow = rowBase + r;
        bool rv = grow < NN;
#pragma unroll
        for (int p = 0; p < 8; p++) {
            int k = (p * 4 + kq) * 4;
            float4 v = rv ? *(const float4*)(X + grow * DD + k)
                          : make_float4(0.f, 0.f, 0.f, 0.f);
            As[(k + 0) * MBLK + r] = v.x;
            As[(k + 1) * MBLK + r] = v.y;
            As[(k + 2) * MBLK + r] = v.z;
            As[(k + 3) * MBLK + r] = v.w;
        }
    }
    __syncthreads();

    float o[8][4];
#pragma unroll
    for (int i = 0; i < 8; i++)
#pragma unroll
        for (int j = 0; j < 4; j++) o[i][j] = 0.f;

    int r0 = ty * 8, c = tx * 4;
#pragma unroll 4
    for (int k = 0; k < DD; k++) {
        float4 a0 = *(const float4*)&As[k * MBLK + r0];
        float4 a1 = *(const float4*)&As[k * MBLK + r0 + 4];
        float4 w = *(const float4*)&Ws[k * DD + c];
        float a[8] = {a0.x, a0.y, a0.z, a0.w, a1.x, a1.y, a1.z, a1.w};
        float wv[4] = {w.x, w.y, w.z, w.w};
#pragma unroll
        for (int i = 0; i < 8; i++)
#pragma unroll
            for (int j = 0; j < 4; j++) o[i][j] = fmaf(a[i], wv[j], o[i][j]);
    }
    float4 bv = *(const float4*)(bias + c);
#pragma unroll
    for (int i = 0; i < 8; i++) {
        int row = rowBase + r0 + i;
        if (row < NN) {
            float4 res;
            res.x = o[i][0] + bv.x;
            res.y = o[i][1] + bv.y;
            res.z = o[i][2] + bv.z;
            res.w = o[i][3] + bv.w;
            *(float4*)(g_h + row * DD + c) = res;
        }
    }
}

// ------------------------- Fused layer MLP ---------------------------------
// stage1: z = z0@W1 + b1 (64x256, 8x8 tile) -> LN -> relu -> Zs (smem)
// stage2: h += Zs@W2 + b2 (64x128, 8x4 tile)
// smem: [Ws 128KB (W1 then W2)] [As 32KB / Zs 64KB aliased] = 192KB dynamic
__global__ __launch_bounds__(256) void k_layer(
    const float* __restrict__ W1, const float* __restrict__ b1,
    const float* __restrict__ lng, const float* __restrict__ lnb,
    const float* __restrict__ W2, const float* __restrict__ b2) {
    extern __shared__ float sm[];
    float* Ws = sm;           // 32768 floats
    float* As = sm + 32768;   // 8192 floats (stage1 only)
    float* Zs = sm + 32768;   // 16384 floats (stage2, aliases As)
    __shared__ float s_b1[D2], s_g[D2], s_bt[D2], s_b2[DD];

    int tid = threadIdx.x;
    int tx = tid & 31, ty = tid >> 5;
    int rowBase = blockIdx.x * MBLK;

    s_b1[tid] = b1[tid];
    s_g[tid] = lng[tid];
    s_bt[tid] = lnb[tid];
    if (tid < DD) s_b2[tid] = b2[tid];

    {   // W1 [128][256] -> smem
        const float4* Wv = (const float4*)W1;
        float4* Sv = (float4*)Ws;
#pragma unroll
        for (int i = 0; i < 32; i++) Sv[tid + i * 256] = Wv[tid + i * 256];
    }
    {   // z0 tile transposed: As[k][r]
        int r = tid & 63, kq = tid >> 6;
        int grow = rowBase + r;
        bool rv = grow < NN;
#pragma unroll
        for (int p = 0; p < 8; p++) {
            int k = (p * 4 + kq) * 4;
            float4 v = rv ? *(const float4*)(g_z0 + grow * DD + k)
                          : make_float4(0.f, 0.f, 0.f, 0.f);
            As[(k + 0) * MBLK + r] = v.x;
            As[(k + 1) * MBLK + r] = v.y;
            As[(k + 2) * MBLK + r] = v.z;
            As[(k + 3) * MBLK + r] = v.w;
        }
    }
    __syncthreads();

    float acc[8][8];
#pragma unroll
    for (int i = 0; i < 8; i++)
#pragma unroll
        for (int j = 0; j < 8; j++) acc[i][j] = 0.f;

    int r0 = ty * 8, c0 = tx * 8;
#pragma unroll 2
    for (int k = 0; k < DD; k++) {
        float4 a0 = *(const float4*)&As[k * MBLK + r0];
        float4 a1 = *(const float4*)&As[k * MBLK + r0 + 4];
        float4 w0 = *(const float4*)&Ws[k * D2 + c0];
        float4 w1 = *(const float4*)&Ws[k * D2 + c0 + 4];
        float a[8] = {a0.x, a0.y, a0.z, a0.w, a1.x, a1.y, a1.z, a1.w};
        float w[8] = {w0.x, w0.y, w0.z, w0.w, w1.x, w1.y, w1.z, w1.w};
#pragma unroll
        for (int i = 0; i < 8; i++)
#pragma unroll
            for (int j = 0; j < 8; j++) acc[i][j] = fmaf(a[i], w[j], acc[i][j]);
    }

    // bias + LayerNorm (row = 256 cols, owned by one warp) + relu
#pragma unroll
    for (int i = 0; i < 8; i++) {
        float s = 0.f, s2 = 0.f;
#pragma unroll
        for (int j = 0; j < 8; j++) {
            float z = acc[i][j] + s_b1[c0 + j];
            acc[i][j] = z;
            s += z;
            s2 += z * z;
        }
#pragma unroll
        for (int off = 16; off; off >>= 1) {
            s += __shfl_xor_sync(0xffffffffu, s, off);
            s2 += __shfl_xor_sync(0xffffffffu, s2, off);
        }
        float mu = s * (1.f / D2);
        float var = s2 * (1.f / D2) - mu * mu;
        float rs = rsqrtf(var + 1e-5f);
#pragma unroll
        for (int j = 0; j < 8; j++) {
            float zn = (acc[i][j] - mu) * rs * s_g[c0 + j] + s_bt[c0 + j];
            acc[i][j] = fmaxf(zn, 0.f);
        }
    }
    __syncthreads();  // all warps done with W1/As before aliasing

    // stash relu(LN(z)) -> Zs[r][c]; load W2 [256][128] over W1
#pragma unroll
    for (int i = 0; i < 8; i++) {
        *(float4*)&Zs[(r0 + i) * D2 + c0] =
            make_float4(acc[i][0], acc[i][1], acc[i][2], acc[i][3]);
        *(float4*)&Zs[(r0 + i) * D2 + c0 + 4] =
            make_float4(acc[i][4], acc[i][5], acc[i][6], acc[i][7]);
    }
    {
        const float4* Wv = (const float4*)W2;
        float4* Sv = (float4*)Ws;
#pragma unroll
        for (int i = 0; i < 32; i++) Sv[tid + i * 256] = Wv[tid + i * 256];
    }
    __syncthreads();

    float o[8][4];
#pragma unroll
    for (int i = 0; i < 8; i++)
#pragma unroll
        for (int j = 0; j < 4; j++) o[i][j] = 0.f;

    int c2 = tx * 4;
#pragma unroll 2
    for (int k = 0; k < D2; k++) {
        float4 w = *(const float4*)&Ws[k * DD + c2];
        float wv[4] = {w.x, w.y, w.z, w.w};
#pragma unroll
        for (int i = 0; i < 8; i++) {
            float a = Zs[(r0 + i) * D2 + k];  // warp-broadcast
#pragma unroll
            for (int j = 0; j < 4; j++) o[i][j] = fmaf(a, wv[j], o[i][j]);
        }
    }
#pragma unroll
    for (int i = 0; i < 8; i++) {
        int row = rowBase + r0 + i;
        if (row < NN) {
            float4* hp = (float4*)(g_h + row * DD + c2);
            float4 hv = *hp;
            hv.x += o[i][0] + s_b2[c2 + 0];
            hv.y += o[i][1] + s_b2[c2 + 1];
            hv.z += o[i][2] + s_b2[c2 + 2];
            hv.w += o[i][3] + s_b2[c2 + 3];
            *hp = hv;
        }
    }
}

// ------------------------------ Pool + head --------------------------------
__global__ __launch_bounds__(512) void k_pool() {
    int gi = blockIdx.x;
    int tid = threadIdx.x;
    int rep = tid >> 7, c = tid & 127;
    int s = g_gstart[gi], e = g_gstart[gi + 1];
    float acc = 0.f;
    for (int r = s + rep; r < e; r += 4) acc += g_h[r * DD + c];
    __shared__ float red[512];
    red[tid] = acc;
    __syncthreads();
    if (rep == 0)
        g_pool[gi * DD + c] = red[c] + red[128 + c] + red[256 + c] + red[384 + c];
}

__global__ __launch_bounds__(256) void k_out(const float* __restrict__ W1,
                                             const float* __restrict__ b1,
                                             const float* __restrict__ W2,
                                             const float* __restrict__ b2,
                                             float* __restrict__ out) {
    __shared__ float gs[DD];
    __shared__ float ts[D2];
    int gi = blockIdx.x, tid = threadIdx.x;
    if (tid < DD) gs[tid] = g_pool[gi * DD + tid];
    __syncthreads();
    float a = b1[tid];
    for (int k = 0; k < DD; k++) a = fmaf(gs[k], W1[k * D2 + tid], a);
    ts[tid] = fmaxf(a, 0.f);
    __syncthreads();
    if (tid < NO) {
        float o = b2[tid];
        for (int k = 0; k < D2; k++) o = fmaf(ts[k], W2[k * NO + tid], o);
        out[gi * NO + tid] = o;
    }
}

// ------------------------------ Launch -------------------------------------
extern "C" void kernel_launch(void* const* d_in, const int* in_sizes, int n_in,
                              void* d_out, int out_size) {
    const float* x = (const float*)d_in[0];
    const int* ei = (const int*)d_in[1];
    const int* batch = (const int*)d_in[2];
    const float* lin_w = (const float*)d_in[3];
    const float* lin_b = (const float*)d_in[4];
    const float* cw1 = (const float*)d_in[5];
    const float* cb1 = (const float*)d_in[6];
    const float* clng = (const float*)d_in[7];
    const float* clnb = (const float*)d_in[8];
    const float* cw2 = (const float*)d_in[9];
    const float* cb2 = (const float*)d_in[10];
    const float* ceps = (const float*)d_in[11];
    const float* ow1 = (const float*)d_in[12];
    const float* ob1 = (const float*)d_in[13];
    const float* ow2 = (const float*)d_in[14];
    const float* ob2 = (const float*)d_in[15];
    float* out = (float*)d_out;

    cudaFuncSetAttribute(k_layer, cudaFuncAttributeMaxDynamicSharedMemorySize,
                         196608);
    cudaFuncSetAttribute(k_lin, cudaFuncAttributeMaxDynamicSharedMemorySize,
                         98304);

    // CSR by destination + graph boundaries (rebuilt every launch; no caching)
    k_zero<<<(NN + 255) / 256, 256>>>();
    k_hist<<<(NE + 255) / 256, 256>>>(ei);
    k_scan<<<1, 1024>>>();
    k_place<<<(NE + 255) / 256, 256>>>(ei);
    k_gstart<<<(NN + 255) / 256, 256>>>(batch);

    int gblk = (NN + MBLK - 1) / MBLK;
    k_lin<<<gblk, 256, 98304>>>(x, lin_w, lin_b);
    for (int l = 0; l < NL; l++) {
        k_agg<<<(NN + 7) / 8, 256>>>(ceps + l);
        k_layer<<<gblk, 256, 196608>>>(cw1 + l * DD * D2, cb1 + l * D2,
                                       clng + l * D2, clnb + l * D2,
                                       cw2 + l * D2 * DD, cb2 + l * DD);
    }
    k_pool<<<NG, 512>>>();
    k_out<<<NG, 256>>>(ow1, ob1, ow2, ob2, out);
}

// round 2
// speedup vs baseline: 1.6376x; 1.6376x over previous
#include <cuda_runtime.h>

// ---------------------------------------------------------------------------
// GIN model. GEMMs on tensor cores (mma.sync m16n8k8 tf32, fp32 accumulate),
// everything else fp32. CSR-by-dst aggregation, fused MLP+LN layer kernel.
// ---------------------------------------------------------------------------

#define NN 50000
#define NE 800000
#define DD 128
#define D2 256
#define NG 64
#define NO 10
#define NL 3
#define MBLK 64

__device__ __align__(16) float g_h[NN * DD];
__device__ __align__(16) float g_z0[NN * DD];
__device__ __align__(16) float g_pool[NG * DD];
__device__ int g_rowptr[NN + 1];
__device__ int g_deg[NN];
__device__ int g_cur[NN];
__device__ int g_srcs[NE];
__device__ int g_gstart[NG + 1];

// ------------------------------ helpers ------------------------------------
__device__ __forceinline__ float to_tf32(float x) {
    unsigned u;
    asm("cvt.rna.tf32.f32 %0, %1;" : "=r"(u) : "f"(x));
    return __uint_as_float(u);
}

__device__ __forceinline__ void mma_tf32(float& d0, float& d1, float& d2,
                                         float& d3, float a0, float a1,
                                         float a2, float a3, float b0,
                                         float b1) {
    unsigned ua0 = __float_as_uint(a0), ua1 = __float_as_uint(a1);
    unsigned ua2 = __float_as_uint(a2), ua3 = __float_as_uint(a3);
    unsigned ub0 = __float_as_uint(b0), ub1 = __float_as_uint(b1);
    asm volatile(
        "mma.sync.aligned.m16n8k8.row.col.f32.tf32.tf32.f32 "
        "{%0,%1,%2,%3}, {%4,%5,%6,%7}, {%8,%9}, {%0,%1,%2,%3};\n"
        : "+f"(d0), "+f"(d1), "+f"(d2), "+f"(d3)
        : "r"(ua0), "r"(ua1), "r"(ua2), "r"(ua3), "r"(ub0), "r"(ub1));
}

// ------------------------------ CSR build ----------------------------------
__global__ void k_zero() {
    int i = blockIdx.x * blockDim.x + threadIdx.x;
    if (i < NN) { g_deg[i] = 0; g_cur[i] = 0; }
}

__global__ void k_hist(const int* __restrict__ ei) {
    int e = blockIdx.x * blockDim.x + threadIdx.x;
    if (e < NE) atomicAdd(&g_deg[ei[NE + e]], 1);
}

__global__ void k_scan() {
    __shared__ int part[1024];
    int tid = threadIdx.x;
    const int CH = (NN + 1023) / 1024;
    int base = tid * CH;
    int s = 0;
    for (int i = 0; i < CH; i++) { int idx = base + i; if (idx < NN) s += g_deg[idx]; }
    part[tid] = s;
    __syncthreads();
    for (int off = 1; off < 1024; off <<= 1) {
        int v = (tid >= off) ? part[tid - off] : 0;
        __syncthreads();
        part[tid] += v;
        __syncthreads();
    }
    int run = (tid == 0) ? 0 : part[tid - 1];
    for (int i = 0; i < CH; i++) {
        int idx = base + i;
        if (idx < NN) { g_rowptr[idx] = run; run += g_deg[idx]; }
    }
    if (tid == 1023) g_rowptr[NN] = part[1023];
}

__global__ void k_place(const int* __restrict__ ei) {
    int e = blockIdx.x * blockDim.x + threadIdx.x;
    if (e < NE) {
        int s = ei[e], d = ei[NE + e];
        int p = g_rowptr[d] + atomicAdd(&g_cur[d], 1);
        g_srcs[p] = s;
    }
}

__global__ void k_gstart(const int* __restrict__ batch) {
    int i = blockIdx.x * blockDim.x + threadIdx.x;
    if (i >= NN) return;
    int b = batch[i];
    if (i == 0) {
        for (int g = 0; g <= b; g++) g_gstart[g] = 0;
    } else {
        int pb = batch[i - 1];
        for (int g = pb + 1; g <= b; g++) g_gstart[g] = i;
    }
    if (i == NN - 1) {
        for (int g = b + 1; g <= NG; g++) g_gstart[g] = NN;
    }
}

// ------------------------------ Aggregation --------------------------------
__global__ __launch_bounds__(256) void k_agg(const float* __restrict__ eps) {
    int node = blockIdx.x * 8 + (threadIdx.x >> 5);
    int lane = threadIdx.x & 31;
    if (node >= NN) return;
    int s = g_rowptr[node], e = g_rowptr[node + 1];
    float4 acc = make_float4(0.f, 0.f, 0.f, 0.f);
    for (int i = s; i < e; i++) {
        int src = g_srcs[i];
        float4 v = *(const float4*)(g_h + src * DD + lane * 4);
        acc.x += fmaxf(v.x, 0.f);
        acc.y += fmaxf(v.y, 0.f);
        acc.z += fmaxf(v.z, 0.f);
        acc.w += fmaxf(v.w, 0.f);
    }
    float k1 = 1.0f + eps[0];
    float4 hv = *(const float4*)(g_h + node * DD + lane * 4);
    float4 o;
    o.x = fmaf(k1, hv.x, acc.x);
    o.y = fmaf(k1, hv.y, acc.y);
    o.z = fmaf(k1, hv.z, acc.z);
    o.w = fmaf(k1, hv.w, acc.w);
    *(float4*)(g_z0 + node * DD + lane * 4) = o;
}

// ------------------------------ Input GEMM (TC) -----------------------------
// h = x @ Win + bin.  64-row CTA, 256 thr. Warps: 2(M)x4(N), warp=32x32.
// Strides: A 132 (4 mod 32), W 136 (8 mod 32) -> conflict-free fragments.
#define LAW 132
#define LWW 136
__global__ __launch_bounds__(256) void k_lin(const float* __restrict__ X,
                                             const float* __restrict__ W,
                                             const float* __restrict__ bias) {
    extern __shared__ float sm[];
    float* Ws = sm;               // 128*136
    float* As = sm + DD * LWW;    // 64*132
    int tid = threadIdx.x;
    int lane = tid & 31, wid = tid >> 5;
    int g = lane >> 2, t4 = lane & 3;
    int rowBase = blockIdx.x * MBLK;

#pragma unroll
    for (int i = 0; i < 64; i++) {
        int idx = tid + i * 256;
        int k = idx >> 7, n = idx & 127;
        Ws[k * LWW + n] = to_tf32(W[idx]);
    }
#pragma unroll
    for (int i = 0; i < 32; i++) {
        int idx = tid + i * 256;
        int r = idx >> 7, k = idx & 127;
        int row = rowBase + r;
        As[r * LAW + k] = (row < NN) ? to_tf32(X[row * DD + k]) : 0.f;
    }
    __syncthreads();

    int mb = (wid & 1) * 32;
    int nb = (wid >> 1) * 32;
    float acc[2][4][4];
#pragma unroll
    for (int a = 0; a < 2; a++)
#pragma unroll
        for (int b = 0; b < 4; b++)
#pragma unroll
            for (int c = 0; c < 4; c++) acc[a][b][c] = 0.f;

#pragma unroll
    for (int ks = 0; ks < 16; ks++) {
        int k0 = ks * 8;
        float af[2][4];
#pragma unroll
        for (int mt = 0; mt < 2; mt++) {
            const float* ap = As + (mb + mt * 16 + g) * LAW + k0 + t4;
            af[mt][0] = ap[0];
            af[mt][1] = ap[8 * LAW];
            af[mt][2] = ap[4];
            af[mt][3] = ap[8 * LAW + 4];
        }
#pragma unroll
        for (int nt = 0; nt < 4; nt++) {
            const float* bp = Ws + (k0 + t4) * LWW + nb + nt * 8 + g;
            float b0 = bp[0], b1 = bp[4 * LWW];
#pragma unroll
            for (int mt = 0; mt < 2; mt++)
                mma_tf32(acc[mt][nt][0], acc[mt][nt][1], acc[mt][nt][2],
                         acc[mt][nt][3], af[mt][0], af[mt][1], af[mt][2],
                         af[mt][3], b0, b1);
        }
    }

#pragma unroll
    for (int mt = 0; mt < 2; mt++) {
        int row = rowBase + mb + mt * 16 + g;
#pragma unroll
        for (int nt = 0; nt < 4; nt++) {
            int col = nb + nt * 8 + t4 * 2;
            float bx = bias[col], by = bias[col + 1];
            if (row < NN) {
                float2 v = make_float2(acc[mt][nt][0] + bx, acc[mt][nt][1] + by);
                *(float2*)(g_h + row * DD + col) = v;
            }
            if (row + 8 < NN) {
                float2 v = make_float2(acc[mt][nt][2] + bx, acc[mt][nt][3] + by);
                *(float2*)(g_h + (row + 8) * DD + col) = v;
            }
        }
    }
}

// ------------------------- Fused layer MLP (TC) -----------------------------
// stage1: z = z0@W1+b1 (64x256) -> LN -> relu -> Zs smem
// stage2: h += Zs@W2+b2 (64x128)
// smem: Ws cap 34816 floats (W1:128*264 / W2:256*136), Zs 64*260 over As 64*132.
#define L1W 264
#define L2W 136
#define LZW 260
#define WS_CAP 34816
__global__ __launch_bounds__(256) void k_layer(
    const float* __restrict__ W1, const float* __restrict__ b1,
    const float* __restrict__ lng, const float* __restrict__ lnb,
    const float* __restrict__ W2, const float* __restrict__ b2) {
    extern __shared__ float sm[];
    float* Ws = sm;
    float* As = sm + WS_CAP;
    float* Zs = sm + WS_CAP;
    __shared__ float s_s[64][4];
    __shared__ float s_q[64][4];

    int tid = threadIdx.x;
    int lane = tid & 31, wid = tid >> 5;
    int g = lane >> 2, t4 = lane & 3;
    int rowBase = blockIdx.x * MBLK;
    int warpM = wid & 1, warpN = wid >> 1;
    int mb = warpM * 32;

    // W1 [128][256] -> Ws (tf32), z0 tile -> As (tf32)
#pragma unroll
    for (int i = 0; i < 128; i++) {
        int idx = tid + i * 256;
        int k = idx >> 8, n = idx & 255;
        Ws[k * L1W + n] = to_tf32(W1[idx]);
    }
#pragma unroll
    for (int i = 0; i < 32; i++) {
        int idx = tid + i * 256;
        int r = idx >> 7, k = idx & 127;
        int row = rowBase + r;
        As[r * LAW + k] = (row < NN) ? to_tf32(g_z0[row * DD + k]) : 0.f;
    }
    __syncthreads();

    // ---------------- stage 1: 64x256 @ K=128 ----------------
    int nb = warpN * 64;  // 8 n-tiles
    float acc[2][8][4];
#pragma unroll
    for (int a = 0; a < 2; a++)
#pragma unroll
        for (int b = 0; b < 8; b++)
#pragma unroll
            for (int c = 0; c < 4; c++) acc[a][b][c] = 0.f;

#pragma unroll
    for (int ks = 0; ks < 16; ks++) {
        int k0 = ks * 8;
        float af[2][4];
#pragma unroll
        for (int mt = 0; mt < 2; mt++) {
            const float* ap = As + (mb + mt * 16 + g) * LAW + k0 + t4;
            af[mt][0] = ap[0];
            af[mt][1] = ap[8 * LAW];
            af[mt][2] = ap[4];
            af[mt][3] = ap[8 * LAW + 4];
        }
#pragma unroll
        for (int nt = 0; nt < 8; nt++) {
            const float* bp = Ws + (k0 + t4) * L1W + nb + nt * 8 + g;
            float b0 = bp[0], b1 = bp[4 * L1W];
#pragma unroll
            for (int mt = 0; mt < 2; mt++)
                mma_tf32(acc[mt][nt][0], acc[mt][nt][1], acc[mt][nt][2],
                         acc[mt][nt][3], af[mt][0], af[mt][1], af[mt][2],
                         af[mt][3], b0, b1);
        }
    }

    // bias + per-row partial LN stats over this warp's 64 cols
#pragma unroll
    for (int mt = 0; mt < 2; mt++) {
#pragma unroll
        for (int h = 0; h < 2; h++) {
            float s = 0.f, q = 0.f;
#pragma unroll
            for (int nt = 0; nt < 8; nt++) {
                int col = nb + nt * 8 + t4 * 2;
                float z0v = acc[mt][nt][2 * h + 0] + b1[col];
                float z1v = acc[mt][nt][2 * h + 1] + b1[col + 1];
                acc[mt][nt][2 * h + 0] = z0v;
                acc[mt][nt][2 * h + 1] = z1v;
                s += z0v + z1v;
                q += z0v * z0v + z1v * z1v;
            }
            s += __shfl_xor_sync(0xffffffffu, s, 1);
            q += __shfl_xor_sync(0xffffffffu, q, 1);
            s += __shfl_xor_sync(0xffffffffu, s, 2);
            q += __shfl_xor_sync(0xffffffffu, q, 2);
            if (t4 == 0) {
                int r = mb + mt * 16 + h * 8 + g;
                s_s[r][warpN] = s;
                s_q[r][warpN] = q;
            }
        }
    }
    __syncthreads();  // partials ready; all warps past W1/As reads

    // finalize LN + relu; write Zs (tf32); reload Ws with W2
#pragma unroll
    for (int mt = 0; mt < 2; mt++) {
#pragma unroll
        for (int h = 0; h < 2; h++) {
            int r = mb + mt * 16 + h * 8 + g;
            float s = s_s[r][0] + s_s[r][1] + s_s[r][2] + s_s[r][3];
            float q = s_q[r][0] + s_q[r][1] + s_q[r][2] + s_q[r][3];
            float mu = s * (1.f / D2);
            float var = q * (1.f / D2) - mu * mu;
            float rs = rsqrtf(var + 1e-5f);
#pragma unroll
            for (int nt = 0; nt < 8; nt++) {
                int col = nb + nt * 8 + t4 * 2;
                float z0v = (acc[mt][nt][2 * h + 0] - mu) * rs * lng[col] + lnb[col];
                float z1v = (acc[mt][nt][2 * h + 1] - mu) * rs * lng[col + 1] + lnb[col + 1];
                float2 zz = make_float2(to_tf32(fmaxf(z0v, 0.f)),
                                        to_tf32(fmaxf(z1v, 0.f)));
                *(float2*)(Zs + r * LZW + col) = zz;
            }
        }
    }
#pragma unroll
    for (int i = 0; i < 128; i++) {
        int idx = tid + i * 256;
        int k = idx >> 7, n = idx & 127;
        Ws[k * L2W + n] = to_tf32(W2[idx]);
    }
    __syncthreads();

    // ---------------- stage 2: 64x128 @ K=256 ----------------
    int nb2 = warpN * 32;  // 4 n-tiles
    float acc2[2][4][4];
#pragma unroll
    for (int a = 0; a < 2; a++)
#pragma unroll
        for (int b = 0; b < 4; b++)
#pragma unroll
            for (int c = 0; c < 4; c++) acc2[a][b][c] = 0.f;

#pragma unroll
    for (int ks = 0; ks < 32; ks++) {
        int k0 = ks * 8;
        float af[2][4];
#pragma unroll
        for (int mt = 0; mt < 2; mt++) {
            const float* ap = Zs + (mb + mt * 16 + g) * LZW + k0 + t4;
            af[mt][0] = ap[0];
            af[mt][1] = ap[8 * LZW];
            af[mt][2] = ap[4];
            af[mt][3] = ap[8 * LZW + 4];
        }
#pragma unroll
        for (int nt = 0; nt < 4; nt++) {
            const float* bp = Ws + (k0 + t4) * L2W + nb2 + nt * 8 + g;
            float b0 = bp[0], b1 = bp[4 * L2W];
#pragma unroll
            for (int mt = 0; mt < 2; mt++)
                mma_tf32(acc2[mt][nt][0], acc2[mt][nt][1], acc2[mt][nt][2],
                         acc2[mt][nt][3], af[mt][0], af[mt][1], af[mt][2],
                         af[mt][3], b0, b1);
        }
    }

    // epilogue: h += z + b2
#pragma unroll
    for (int mt = 0; mt < 2; mt++) {
        int row = rowBase + mb + mt * 16 + g;
#pragma unroll
        for (int nt = 0; nt < 4; nt++) {
            int col = nb2 + nt * 8 + t4 * 2;
            float bx = b2[col], by = b2[col + 1];
            if (row < NN) {
                float2* hp = (float2*)(g_h + row * DD + col);
                float2 hv = *hp;
                hv.x += acc2[mt][nt][0] + bx;
                hv.y += acc2[mt][nt][1] + by;
                *hp = hv;
            }
            if (row + 8 < NN) {
                float2* hp = (float2*)(g_h + (row + 8) * DD + col);
                float2 hv = *hp;
                hv.x += acc2[mt][nt][2] + bx;
                hv.y += acc2[mt][nt][3] + by;
                *hp = hv;
            }
        }
    }
}

// ------------------------------ Pool + head --------------------------------
__global__ __launch_bounds__(512) void k_pool() {
    int gi = blockIdx.x;
    int tid = threadIdx.x;
    int rep = tid >> 7, c = tid & 127;
    int s = g_gstart[gi], e = g_gstart[gi + 1];
    float acc = 0.f;
    for (int r = s + rep; r < e; r += 4) acc += g_h[r * DD + c];
    __shared__ float red[512];
    red[tid] = acc;
    __syncthreads();
    if (rep == 0)
        g_pool[gi * DD + c] = red[c] + red[128 + c] + red[256 + c] + red[384 + c];
}

__global__ __launch_bounds__(256) void k_out(const float* __restrict__ W1,
                                             const float* __restrict__ b1,
                                             const float* __restrict__ W2,
                                             const float* __restrict__ b2,
                                             float* __restrict__ out) {
    __shared__ float gs[DD];
    __shared__ float ts[D2];
    int gi = blockIdx.x, tid = threadIdx.x;
    if (tid < DD) gs[tid] = g_pool[gi * DD + tid];
    __syncthreads();
    float a = b1[tid];
    for (int k = 0; k < DD; k++) a = fmaf(gs[k], W1[k * D2 + tid], a);
    ts[tid] = fmaxf(a, 0.f);
    __syncthreads();
    if (tid < NO) {
        float o = b2[tid];
        for (int k = 0; k < D2; k++) o = fmaf(ts[k], W2[k * NO + tid], o);
        out[gi * NO + tid] = o;
    }
}

// ------------------------------ Launch -------------------------------------
extern "C" void kernel_launch(void* const* d_in, const int* in_sizes, int n_in,
                              void* d_out, int out_size) {
    const float* x = (const float*)d_in[0];
    const int* ei = (const int*)d_in[1];
    const int* batch = (const int*)d_in[2];
    const float* lin_w = (const float*)d_in[3];
    const float* lin_b = (const float*)d_in[4];
    const float* cw1 = (const float*)d_in[5];
    const float* cb1 = (const float*)d_in[6];
    const float* clng = (const float*)d_in[7];
    const float* clnb = (const float*)d_in[8];
    const float* cw2 = (const float*)d_in[9];
    const float* cb2 = (const float*)d_in[10];
    const float* ceps = (const float*)d_in[11];
    const float* ow1 = (const float*)d_in[12];
    const float* ob1 = (const float*)d_in[13];
    const float* ow2 = (const float*)d_in[14];
    const float* ob2 = (const float*)d_in[15];
    float* out = (float*)d_out;

    const int lin_smem = (DD * LWW + MBLK * LAW) * 4;           // 103424 B
    const int layer_smem = (WS_CAP + MBLK * LZW) * 4;           // 205824 B
    cudaFuncSetAttribute(k_lin, cudaFuncAttributeMaxDynamicSharedMemorySize,
                         lin_smem);
    cudaFuncSetAttribute(k_layer, cudaFuncAttributeMaxDynamicSharedMemorySize,
                         layer_smem);

    k_zero<<<(NN + 255) / 256, 256>>>();
    k_hist<<<(NE + 255) / 256, 256>>>(ei);
    k_scan<<<1, 1024>>>();
    k_place<<<(NE + 255) / 256, 256>>>(ei);
    k_gstart<<<(NN + 255) / 256, 256>>>(batch);

    int gblk = (NN + MBLK - 1) / MBLK;
    k_lin<<<gblk, 256, lin_smem>>>(x, lin_w, lin_b);
    for (int l = 0; l < NL; l++) {
        k_agg<<<(NN + 7) / 8, 256>>>(ceps + l);
        k_layer<<<gblk, 256, layer_smem>>>(cw1 + l * DD * D2, cb1 + l * D2,
                                           clng + l * D2, clnb + l * D2,
                                           cw2 + l * D2 * DD, cb2 + l * DD);
    }
    k_pool<<<NG, 512>>>();
    k_out<<<NG, 256>>>(ow1, ob1, ow2, ob2, out);
}